// round 16
// baseline (speedup 1.0000x reference)
#include <cuda_runtime.h>
#include <cuda_fp16.h>
#include <cstdint>
#include <cstddef>

#define BATCH 8
#define SEQ   4096
#define HID   1024
#define NHEAD 16
#define MROWS (BATCH * SEQ)   // 32768

// ---------------- scratch (device globals; allocations forbidden) ----------
__device__ __half g_xh[(size_t)MROWS * HID];
__device__ __half g_mqh[(size_t)MROWS * HID];
__device__ __half g_mkh[(size_t)MROWS * HID];
__device__ __half g_wqh[(size_t)HID * HID];
__device__ __half g_wkh[(size_t)HID * HID];
__device__ __half g_wtgh[(size_t)BATCH * HID * HID];
__device__ float  g_qs[(size_t)MROWS * NHEAD];
__device__ float  g_ks[(size_t)MROWS * NHEAD];
__device__ float  g_pq[BATCH * HID];
__device__ float  g_pk[BATCH * HID];
__device__ float  g_part[(size_t)BATCH * NHEAD * 128 * 64];  // 4 MB
__device__ float2 g_ms[BATCH * NHEAD * 128];

#define LDSM_X4(r0, r1, r2, r3, addr)                                             \
    asm volatile("ldmatrix.sync.aligned.m8n8.x4.shared.b16 {%0,%1,%2,%3}, [%4];"  \
                 : "=r"(r0), "=r"(r1), "=r"(r2), "=r"(r3) : "r"(addr))

#define BAR_ARRIVE(id) asm volatile("bar.arrive %0, 256;" :: "r"(id) : "memory")
#define BAR_SYNCN(id)  asm volatile("bar.sync %0, 256;"   :: "r"(id) : "memory")

// ============================================================================
// fp16 GEMM: acc[m,n] = sum_k A[m,k]*W[n,k]; out = acc*sc + bias (+resid)
// BM=64, BN=128, BK=64; 128 thr (4 warps, 2x2 grid, warp tile 32x64);
// 2-stage cp.async with split producer/consumer named barriers.
// 4 CTAs/SM (55.3KB smem, <=128 regs).   [round-13 verified-best config]
// ============================================================================
constexpr int BM = 64, BN = 128, BK = 64;
constexpr int SROW = 72;                      // halves per smem row (144B, padded)
constexpr int NKB = HID / BK;                 // 16
constexpr int STGH = (BM + BN) * SROW;        // 13824 halves per stage
constexpr size_t GEMM_SMEM = (size_t)2 * STGH * sizeof(__half);  // 55296 B

template <bool DUAL, bool PERB, bool OUTH, bool SCALED>
__global__ void __launch_bounds__(128, 4) gemm_fp16(
    const __half* __restrict__ A, const __half* __restrict__ W0, const __half* __restrict__ W1,
    const float* __restrict__ b0, const float* __restrict__ b1,
    const __half* __restrict__ residH, float* __restrict__ Cf,
    __half* __restrict__ H0, __half* __restrict__ H1)
{
    extern __shared__ __half smh[];
    const int tid = threadIdx.x;
    const int m0 = blockIdx.y * BM;
    int nb = blockIdx.x;

    const __half* W; const float* bias; __half* H = H0;
    if (DUAL) {
        if (nb < 8) { W = W0; bias = b0; H = H0; }
        else        { nb -= 8; W = W1; bias = b1; H = H1; }
    } else {
        W = W0 + (PERB ? (size_t)(m0 / SEQ) * HID * HID : 0);
        bias = b0;
    }
    const int n0 = nb * BN;

    const int warp = tid >> 5, lane = tid & 31;
    const int wm = warp & 1, wn = warp >> 1;    // 2x2 warps -> 32x64 per warp
    const int grp = lane >> 2, qid = lane & 3;

    const int lr = lane & 7;
    const int lh = (lane >> 3) & 1;
    const int lk = (lane >> 4) & 1;

    uint32_t offA[2], offB[4];
#pragma unroll
    for (int mt = 0; mt < 2; mt++)
        offA[mt] = (uint32_t)(((wm * 32 + mt * 16 + lh * 8 + lr) * SROW + lk * 8) * 2);
#pragma unroll
    for (int p = 0; p < 4; p++)
        offB[p] = (uint32_t)(((wn * 64 + p * 16 + lk * 8 + lr) * SROW + lh * 8) * 2
                             + BM * SROW * 2);

    const uint32_t smBase = (uint32_t)__cvta_generic_to_shared(smh);

    float acc[2][8][4];
#pragma unroll
    for (int i = 0; i < 2; i++)
#pragma unroll
        for (int j = 0; j < 8; j++)
#pragma unroll
            for (int l = 0; l < 4; l++) acc[i][j][l] = 0.f;

    const __half* Ab = A + (size_t)m0 * HID;
    const __half* Wb = W + (size_t)n0 * HID;

    auto loadTile = [&](int kb, int s) {
        __half* sa = smh + s * STGH;
        __half* sb = sa + BM * SROW;
        const __half* Ag = Ab + kb * BK;
        const __half* Wg = Wb + kb * BK;
#pragma unroll
        for (int i = 0; i < 12; i++) {         // 1536 granules of 16B
            const int id = tid + 128 * i;
            if (id < 512) {                    // A: 64 rows x 8 granules
                const int r = id >> 3, c = id & 7;
                uint32_t d = (uint32_t)__cvta_generic_to_shared(sa + r * SROW + c * 8);
                asm volatile("cp.async.cg.shared.global [%0], [%1], 16;"
                             :: "r"(d), "l"(Ag + (size_t)r * HID + c * 8));
            } else {                           // B: 128 rows x 8 granules
                const int id2 = id - 512;
                const int r = id2 >> 3, c = id2 & 7;
                uint32_t d = (uint32_t)__cvta_generic_to_shared(sb + r * SROW + c * 8);
                asm volatile("cp.async.cg.shared.global [%0], [%1], 16;"
                             :: "r"(d), "l"(Wg + (size_t)r * HID + c * 8));
            }
        }
        asm volatile("cp.async.commit_group;");
    };

    loadTile(0, 0);

    for (int kb = 0; kb < NKB; kb++) {
        const int b = kb & 1, onb = b ^ 1;
        asm volatile("cp.async.wait_group 0;");   // my loads for tile kb landed
        BAR_ARRIVE(1 + b);                        // A_b: my data for kb ready
        if (kb >= 1) BAR_SYNCN(3 + onb);          // F_onb: buffer onb freed
        if (kb + 1 < NKB) loadTile(kb + 1, onb);
        BAR_SYNCN(1 + b);                         // A_b: ALL data for kb visible

        const uint32_t stBase = smBase + b * (STGH * 2);

#pragma unroll
        for (int ks = 0; ks < 4; ks++) {
            const uint32_t kkb = ks * 32;
            uint32_t af[2][4], bf[8][2];
#pragma unroll
            for (int mt = 0; mt < 2; mt++)
                LDSM_X4(af[mt][0], af[mt][1], af[mt][2], af[mt][3],
                        stBase + offA[mt] + kkb);
#pragma unroll
            for (int p = 0; p < 4; p++)
                LDSM_X4(bf[2 * p][0], bf[2 * p][1], bf[2 * p + 1][0], bf[2 * p + 1][1],
                        stBase + offB[p] + kkb);
#pragma unroll
            for (int mt = 0; mt < 2; mt++)
#pragma unroll
                for (int nt = 0; nt < 8; nt++) {
                    asm volatile(
                        "mma.sync.aligned.m16n8k16.row.col.f32.f16.f16.f32 "
                        "{%0,%1,%2,%3}, {%4,%5,%6,%7}, {%8,%9}, {%0,%1,%2,%3};"
                        : "+f"(acc[mt][nt][0]), "+f"(acc[mt][nt][1]),
                          "+f"(acc[mt][nt][2]), "+f"(acc[mt][nt][3])
                        : "r"(af[mt][0]), "r"(af[mt][1]), "r"(af[mt][2]), "r"(af[mt][3]),
                          "r"(bf[nt][0]), "r"(bf[nt][1]));
                }
        }
        BAR_ARRIVE(3 + b);                        // F_b: I'm done reading buffer b
    }

    const float sc = SCALED ? 6.103515625e-5f : 1.0f;   // 2^-14

    // epilogue
#pragma unroll
    for (int mt = 0; mt < 2; mt++) {
        const int r0 = m0 + wm * 32 + mt * 16 + grp;
#pragma unroll
        for (int nt = 0; nt < 8; nt++) {
            const int c = n0 + wn * 64 + nt * 8 + qid * 2;
            const float bv0 = bias[c], bv1 = bias[c + 1];
            float v0 = acc[mt][nt][0] * sc + bv0, v1 = acc[mt][nt][1] * sc + bv1;
            float v2 = acc[mt][nt][2] * sc + bv0, v3 = acc[mt][nt][3] * sc + bv1;
            if (OUTH) {
                *(__half2*)(H + (size_t)r0 * HID + c)       = __floats2half2_rn(v0, v1);
                *(__half2*)(H + (size_t)(r0 + 8) * HID + c) = __floats2half2_rn(v2, v3);
            } else {
                __half2 ra = *(const __half2*)(residH + (size_t)r0 * HID + c);
                __half2 rb = *(const __half2*)(residH + (size_t)(r0 + 8) * HID + c);
                float2 raf = __half22float2(ra), rbf = __half22float2(rb);
                float2 oa = {v0 + raf.x, v1 + raf.y};
                float2 ob = {v2 + rbf.x, v3 + rbf.y};
                *(float2*)(Cf + (size_t)r0 * HID + c) = oa;
                *(float2*)(Cf + (size_t)(r0 + 8) * HID + c) = ob;
            }
        }
    }
}

// ============================================================================
// score_mma: out[m,h] = sum_k src[m,k]*(W[h,k]*(gate?g[b,k]:1)) + bias[h]
// Tensor-core skinny GEMM (N=16). Gated W resident in smem as fp16.
// ============================================================================
constexpr int SC_WROW = 1032;
constexpr int SC_SROW = 72;
constexpr int SC_NKT  = HID / 64;
constexpr size_t SC_SMEM = (size_t)(16 * SC_WROW + 3 * 128 * SC_SROW) * 2; // 88320 B

__global__ void __launch_bounds__(256, 2) score_mma(
    const __half* __restrict__ src, const float* __restrict__ W,
    const float* __restrict__ bias, const float* __restrict__ gate,
    float* __restrict__ out)
{
    extern __shared__ __half ssc[];
    __half* sWg = ssc;                        // 16 x 1032
    __half* sA  = ssc + 16 * SC_WROW;         // 3 x 128 x 72
    const int tid = threadIdx.x, warp = tid >> 5, lane = tid & 31;
    const int row0 = blockIdx.x * 128;
    const int b = row0 / SEQ;

    for (int i = tid; i < NHEAD * HID; i += 256) {
        const int h = i >> 10, k = i & 1023;
        float w = W[i];
        if (gate) w *= gate[b * HID + k];
        sWg[h * SC_WROW + k] = __float2half_rn(w);
    }

    const __half* Ab = src + (size_t)row0 * HID;
    auto loadA = [&](int kt, int s) {
        __half* sa = sA + s * 128 * SC_SROW;
        const __half* Ag = Ab + kt * 64;
#pragma unroll
        for (int i = 0; i < 4; i++) {
            const int id = tid + 256 * i;
            const int r = id >> 3, c = id & 7;
            uint32_t d = (uint32_t)__cvta_generic_to_shared(sa + r * SC_SROW + c * 8);
            asm volatile("cp.async.cg.shared.global [%0], [%1], 16;"
                         :: "r"(d), "l"(Ag + (size_t)r * HID + c * 8));
        }
        asm volatile("cp.async.commit_group;");
    };

    loadA(0, 0);
    loadA(1, 1);
    __syncthreads();

    const int lr = lane & 7;
    const int lh = (lane >> 3) & 1;
    const int lk = lane >> 4;
    const uint32_t offA = (uint32_t)(((warp * 16 + lh * 8 + lr) * SC_SROW + lk * 8) * 2);
    const uint32_t offBW = (uint32_t)(((lk * 8 + lr) * SC_WROW + lh * 8) * 2);
    const uint32_t smA = (uint32_t)__cvta_generic_to_shared(sA);
    const uint32_t smW = (uint32_t)__cvta_generic_to_shared(sWg);

    float acc0[4] = {0.f, 0.f, 0.f, 0.f};
    float acc1[4] = {0.f, 0.f, 0.f, 0.f};

    int s = 0;
    for (int kt = 0; kt < SC_NKT; kt++) {
        if (kt + 1 < SC_NKT) asm volatile("cp.async.wait_group 1;");
        else                 asm volatile("cp.async.wait_group 0;");
        __syncthreads();
        if (kt + 2 < SC_NKT) loadA(kt + 2, (s + 2) % 3);

        const uint32_t stA = smA + s * (128 * SC_SROW * 2);
#pragma unroll
        for (int ks = 0; ks < 4; ks++) {
            uint32_t a0, a1, a2, a3, b0, b1, b2, b3;
            LDSM_X4(a0, a1, a2, a3, stA + offA + ks * 32);
            LDSM_X4(b0, b1, b2, b3, smW + offBW + (uint32_t)((kt * 64 + ks * 16) * 2));
            asm volatile(
                "mma.sync.aligned.m16n8k16.row.col.f32.f16.f16.f32 "
                "{%0,%1,%2,%3}, {%4,%5,%6,%7}, {%8,%9}, {%0,%1,%2,%3};"
                : "+f"(acc0[0]), "+f"(acc0[1]), "+f"(acc0[2]), "+f"(acc0[3])
                : "r"(a0), "r"(a1), "r"(a2), "r"(a3), "r"(b0), "r"(b1));
            asm volatile(
                "mma.sync.aligned.m16n8k16.row.col.f32.f16.f16.f32 "
                "{%0,%1,%2,%3}, {%4,%5,%6,%7}, {%8,%9}, {%0,%1,%2,%3};"
                : "+f"(acc1[0]), "+f"(acc1[1]), "+f"(acc1[2]), "+f"(acc1[3])
                : "r"(a0), "r"(a1), "r"(a2), "r"(a3), "r"(b2), "r"(b3));
        }
        s = (s + 1) % 3;
    }

    const int grp = lane >> 2, qid = lane & 3;
    const int rlo = row0 + warp * 16 + grp;
    float2 bv0 = ((const float2*)bias)[qid];
    float2 bv1 = ((const float2*)bias)[4 + qid];
    float2 o;
    o.x = acc0[0] + bv0.x; o.y = acc0[1] + bv0.y;
    *(float2*)(out + (size_t)rlo * NHEAD + qid * 2) = o;
    o.x = acc0[2] + bv0.x; o.y = acc0[3] + bv0.y;
    *(float2*)(out + (size_t)(rlo + 8) * NHEAD + qid * 2) = o;
    o.x = acc1[0] + bv1.x; o.y = acc1[1] + bv1.y;
    *(float2*)(out + (size_t)rlo * NHEAD + 8 + qid * 2) = o;
    o.x = acc1[2] + bv1.x; o.y = acc1[3] + bv1.y;
    *(float2*)(out + (size_t)(rlo + 8) * NHEAD + 8 + qid * 2) = o;
}

// ============================================================================
// Combined fp32 -> fp16 conversion of X, Wq, Wk in ONE launch
// ============================================================================
constexpr int N4_X = MROWS * HID / 4;         // 8388608
constexpr int N4_W = HID * HID / 4;           // 262144

__global__ void f2h3_kernel(const float* __restrict__ X,
                            const float* __restrict__ Wq,
                            const float* __restrict__ Wk,
                            __half* __restrict__ xh,
                            __half* __restrict__ wqh,
                            __half* __restrict__ wkh)
{
    const int i = blockIdx.x * 256 + threadIdx.x;
    const float* src; __half* dst; int j;
    if (i < N4_X)            { src = X;  dst = xh;  j = i; }
    else if (i < N4_X + N4_W){ src = Wq; dst = wqh; j = i - N4_X; }
    else                     { src = Wk; dst = wkh; j = i - N4_X - N4_W; }
    float4 v = ((const float4*)src)[j];
    ((__half2*)dst)[2 * j]     = __floats2half2_rn(v.x, v.y);
    ((__half2*)dst)[2 * j + 1] = __floats2half2_rn(v.z, v.w);
}

// ============================================================================
// accum: WARP-AUTONOMOUS. One warp per (bh, 32-row chunk); no block barriers.
// Max/sum via shfl_xor; weights broadcast via shfl; half2 pooling, unroll 4.
// Emits unnormalized vec[64] + (m_c, s_c); finalize combines 128 chunks.
// ============================================================================
constexpr int ACH = 128;                      // chunks per (b,h)
constexpr int ACS = SEQ / ACH;                // 32 rows per chunk

__global__ void __launch_bounds__(256, 8) accum_kernel(
    const __half* __restrict__ src,
    const float* __restrict__ scores,
    const float* __restrict__ mask,
    float* __restrict__ part, float2* __restrict__ ms)
{
    const int gw   = (blockIdx.x * 256 + threadIdx.x) >> 5;  // global warp = chunk id
    const int lane = threadIdx.x & 31;
    const int bh = gw >> 7, ch = gw & 127;
    const int b = bh >> 4, h = bh & 15;
    const int s0 = ch * ACS;

    // per-lane logit (one row per lane)
    const int row = b * SEQ + s0 + lane;
    const float l = scores[(size_t)row * NHEAD + h] * 0.125f + mask[row];

    float mc = l;
#pragma unroll
    for (int o = 16; o; o >>= 1) mc = fmaxf(mc, __shfl_xor_sync(0xffffffffu, mc, o));
    const float e = __expf(l - mc);
    float ssum = e;
#pragma unroll
    for (int o = 16; o; o >>= 1) ssum += __shfl_xor_sync(0xffffffffu, ssum, o);

    // pool: lane owns dims (2*lane, 2*lane+1); stream 32 rows
    const __half2* base = (const __half2*)(src + (size_t)(b * SEQ + s0) * HID + h * 64) + lane;
    float2 acc = {0.f, 0.f};
#pragma unroll 4
    for (int s2 = 0; s2 < ACS; s2++) {
        const float w = __shfl_sync(0xffffffffu, e, s2);
        float2 v = __half22float2(base[(size_t)s2 * (HID / 2)]);
        acc.x += w * v.x; acc.y += w * v.y;
    }
    ((float2*)(part + (size_t)gw * 64))[lane] = acc;
    if (lane == 0) ms[gw] = make_float2(mc, ssum);
}

__global__ void finalize_kernel(const float* __restrict__ part,
                                const float2* __restrict__ ms,
                                const float* __restrict__ postgate, float* __restrict__ out)
{
    const int idx = blockIdx.x * 256 + threadIdx.x;   // 8192
    const int bh = idx >> 6, d = idx & 63;
    float M = -1e30f;
    for (int c = 0; c < ACH; c++) M = fmaxf(M, ms[bh * ACH + c].x);
    float num = 0.f, den = 0.f;
    for (int c = 0; c < ACH; c++) {
        const float2 mv = ms[bh * ACH + c];
        const float w = __expf(mv.x - M);
        num += w * part[(size_t)(bh * ACH + c) * 64 + d];
        den += w * mv.y;
    }
    float v = num / den;
    if (postgate) v *= postgate[idx];
    out[idx] = v;
}

// wtgh[b,n,k] = (half)(Wt[n,k] * pk[b,k] * 2^14)   (scale avoids fp16 subnormals)
__global__ void wtg_kernel(const float* __restrict__ Wt, const float* __restrict__ pk,
                           __half* __restrict__ wtgh)
{
    const size_t i4 = (size_t)blockIdx.x * 256 + threadIdx.x;  // 2,097,152
    const int j4 = (int)(i4 & 255);
    const int n  = (int)((i4 >> 8) & 1023);
    const int b  = (int)(i4 >> 18);
    float4 w = ((const float4*)Wt)[n * 256 + j4];
    float4 g = ((const float4*)pk)[b * 256 + j4];
    const float S = 16384.0f;
    __half2 h0 = __floats2half2_rn(w.x * g.x * S, w.y * g.y * S);
    __half2 h1 = __floats2half2_rn(w.z * g.z * S, w.w * g.w * S);
    ((__half2*)wtgh)[2 * i4]     = h0;
    ((__half2*)wtgh)[2 * i4 + 1] = h1;
}

// ============================================================================
extern "C" void kernel_launch(void* const* d_in, const int* in_sizes, int n_in,
                              void* d_out, int out_size)
{
    const float* X    = (const float*)d_in[0];
    const float* mask = (const float*)d_in[1];
    const float* Wq   = (const float*)d_in[2];
    const float* bq   = (const float*)d_in[3];
    const float* Wqa  = (const float*)d_in[4];
    const float* bqa  = (const float*)d_in[5];
    const float* Wk   = (const float*)d_in[6];
    const float* bk   = (const float*)d_in[7];
    const float* Wka  = (const float*)d_in[8];
    const float* bka  = (const float*)d_in[9];
    const float* Wt   = (const float*)d_in[10];
    const float* bt   = (const float*)d_in[11];
    float* out = (float*)d_out;

    float *qs, *ks, *pq, *pk, *part;
    float2 *ms;
    __half *xh, *mqh, *mkh, *wqh, *wkh, *wtgh;
    cudaGetSymbolAddress((void**)&qs, g_qs);
    cudaGetSymbolAddress((void**)&ks, g_ks);
    cudaGetSymbolAddress((void**)&pq, g_pq);
    cudaGetSymbolAddress((void**)&pk, g_pk);
    cudaGetSymbolAddress((void**)&part, g_part);
    cudaGetSymbolAddress((void**)&ms, g_ms);
    cudaGetSymbolAddress((void**)&xh, g_xh);
    cudaGetSymbolAddress((void**)&mqh, g_mqh);
    cudaGetSymbolAddress((void**)&mkh, g_mkh);
    cudaGetSymbolAddress((void**)&wqh, g_wqh);
    cudaGetSymbolAddress((void**)&wkh, g_wkh);
    cudaGetSymbolAddress((void**)&wtgh, g_wtgh);

    cudaFuncSetAttribute(gemm_fp16<true, false, true, false>,
                         cudaFuncAttributeMaxDynamicSharedMemorySize, (int)GEMM_SMEM);
    cudaFuncSetAttribute(gemm_fp16<false, true, false, true>,
                         cudaFuncAttributeMaxDynamicSharedMemorySize, (int)GEMM_SMEM);
    cudaFuncSetAttribute(score_mma,
                         cudaFuncAttributeMaxDynamicSharedMemorySize, (int)SC_SMEM);

    const float* nullf = nullptr;

    // 0) single fused fp32->fp16 conversion (X, Wq, Wk)
    f2h3_kernel<<<(N4_X + 2 * N4_W + 255) / 256, 256>>>(X, Wq, Wk, xh, wqh, wkh);

    // 1) fused: mqh = X@Wq^T + bq ; mkh = X@Wk^T + bk  (fp16 outputs)
    gemm_fp16<true, false, true, false><<<dim3(16, MROWS / BM), 128, GEMM_SMEM>>>(
        xh, wqh, wkh, bq, bk, (const __half*)nullptr, (float*)nullptr, mqh, mkh);

    // 2) q scores -> pooled_q (warp-chunk softmax pooling)
    score_mma<<<MROWS / 128, 256, SC_SMEM>>>(mqh, Wqa, bqa, nullf, qs);
    accum_kernel<<<BATCH * NHEAD * ACH / 8, 256>>>(mqh, qs, mask, part, ms);
    finalize_kernel<<<BATCH * HID / 256, 256>>>(part, ms, nullf, pq);

    // 3) qk scores (gate folded into Wka) -> pooled_k (post-gate pq)
    score_mma<<<MROWS / 128, 256, SC_SMEM>>>(mkh, Wka, bka, pq, ks);
    accum_kernel<<<BATCH * NHEAD * ACH / 8, 256>>>(mkh, ks, mask, part, ms);
    finalize_kernel<<<BATCH * HID / 256, 256>>>(part, ms, pq, pk);

    // 4) wtgh = Wt * pk_full[b] * 2^14 ; out = mqh @ wtgh[b]^T * 2^-14 + bt + mqh
    wtg_kernel<<<(BATCH * HID * HID / 4) / 256, 256>>>(Wt, pk, wtgh);
    gemm_fp16<false, true, false, true><<<dim3(8, MROWS / BM), 128, GEMM_SMEM>>>(
        mqh, wtgh, (const __half*)nullptr, bt, nullf, mqh, out,
        (__half*)nullptr, (__half*)nullptr);
}

// round 17
// speedup vs baseline: 1.0333x; 1.0333x over previous
#include <cuda_runtime.h>
#include <cuda_fp16.h>
#include <cstdint>
#include <cstddef>

#define BATCH 8
#define SEQ   4096
#define HID   1024
#define NHEAD 16
#define MROWS (BATCH * SEQ)   // 32768

// ---------------- scratch (device globals; allocations forbidden) ----------
__device__ __half g_xh[(size_t)MROWS * HID];
__device__ __half g_mqh[(size_t)MROWS * HID];
__device__ __half g_mkh[(size_t)MROWS * HID];
__device__ __half g_wqh[(size_t)HID * HID];
__device__ __half g_wkh[(size_t)HID * HID];
__device__ __half g_wtgh[(size_t)BATCH * HID * HID];
__device__ float  g_qs[(size_t)MROWS * NHEAD];
__device__ float  g_ks[(size_t)MROWS * NHEAD];
__device__ float  g_pq[BATCH * HID];
__device__ float  g_pk[BATCH * HID];
__device__ float  g_part[BATCH * NHEAD * 16 * 64];
__device__ float2 g_ms[BATCH * NHEAD * 16];

#define LDSM_X4(r0, r1, r2, r3, addr)                                             \
    asm volatile("ldmatrix.sync.aligned.m8n8.x4.shared.b16 {%0,%1,%2,%3}, [%4];"  \
                 : "=r"(r0), "=r"(r1), "=r"(r2), "=r"(r3) : "r"(addr))

#define BAR_ARRIVE(id) asm volatile("bar.arrive %0, 256;" :: "r"(id) : "memory")
#define BAR_SYNCN(id)  asm volatile("bar.sync %0, 256;"   :: "r"(id) : "memory")

// ============================================================================
// fp16 GEMM: acc[m,n] = sum_k A[m,k]*W[n,k]; out = acc*sc + bias (+resid)
// BM=64, BN=128, BK=64; 128 thr (4 warps, 2x2 grid, warp tile 32x64);
// 2-stage cp.async with split producer/consumer named barriers.
// 4 CTAs/SM (55.3KB smem, <=128 regs).   [verified-best config, 661.6us total]
// ============================================================================
constexpr int BM = 64, BN = 128, BK = 64;
constexpr int SROW = 72;                      // halves per smem row (144B, padded)
constexpr int NKB = HID / BK;                 // 16
constexpr int STGH = (BM + BN) * SROW;        // 13824 halves per stage
constexpr size_t GEMM_SMEM = (size_t)2 * STGH * sizeof(__half);  // 55296 B

template <bool DUAL, bool PERB, bool OUTH, bool SCALED>
__global__ void __launch_bounds__(128, 4) gemm_fp16(
    const __half* __restrict__ A, const __half* __restrict__ W0, const __half* __restrict__ W1,
    const float* __restrict__ b0, const float* __restrict__ b1,
    const __half* __restrict__ residH, float* __restrict__ Cf,
    __half* __restrict__ H0, __half* __restrict__ H1)
{
    extern __shared__ __half smh[];
    const int tid = threadIdx.x;
    const int m0 = blockIdx.y * BM;
    int nb = blockIdx.x;

    const __half* W; const float* bias; __half* H = H0;
    if (DUAL) {
        if (nb < 8) { W = W0; bias = b0; H = H0; }
        else        { nb -= 8; W = W1; bias = b1; H = H1; }
    } else {
        W = W0 + (PERB ? (size_t)(m0 / SEQ) * HID * HID : 0);
        bias = b0;
    }
    const int n0 = nb * BN;

    const int warp = tid >> 5, lane = tid & 31;
    const int wm = warp & 1, wn = warp >> 1;    // 2x2 warps -> 32x64 per warp
    const int grp = lane >> 2, qid = lane & 3;

    const int lr = lane & 7;
    const int lh = (lane >> 3) & 1;
    const int lk = (lane >> 4) & 1;

    uint32_t offA[2], offB[4];
#pragma unroll
    for (int mt = 0; mt < 2; mt++)
        offA[mt] = (uint32_t)(((wm * 32 + mt * 16 + lh * 8 + lr) * SROW + lk * 8) * 2);
#pragma unroll
    for (int p = 0; p < 4; p++)
        offB[p] = (uint32_t)(((wn * 64 + p * 16 + lk * 8 + lr) * SROW + lh * 8) * 2
                             + BM * SROW * 2);

    const uint32_t smBase = (uint32_t)__cvta_generic_to_shared(smh);

    float acc[2][8][4];
#pragma unroll
    for (int i = 0; i < 2; i++)
#pragma unroll
        for (int j = 0; j < 8; j++)
#pragma unroll
            for (int l = 0; l < 4; l++) acc[i][j][l] = 0.f;

    const __half* Ab = A + (size_t)m0 * HID;
    const __half* Wb = W + (size_t)n0 * HID;

    auto loadTile = [&](int kb, int s) {
        __half* sa = smh + s * STGH;
        __half* sb = sa + BM * SROW;
        const __half* Ag = Ab + kb * BK;
        const __half* Wg = Wb + kb * BK;
#pragma unroll
        for (int i = 0; i < 12; i++) {         // 1536 granules of 16B
            const int id = tid + 128 * i;
            if (id < 512) {                    // A: 64 rows x 8 granules
                const int r = id >> 3, c = id & 7;
                uint32_t d = (uint32_t)__cvta_generic_to_shared(sa + r * SROW + c * 8);
                asm volatile("cp.async.cg.shared.global [%0], [%1], 16;"
                             :: "r"(d), "l"(Ag + (size_t)r * HID + c * 8));
            } else {                           // B: 128 rows x 8 granules
                const int id2 = id - 512;
                const int r = id2 >> 3, c = id2 & 7;
                uint32_t d = (uint32_t)__cvta_generic_to_shared(sb + r * SROW + c * 8);
                asm volatile("cp.async.cg.shared.global [%0], [%1], 16;"
                             :: "r"(d), "l"(Wg + (size_t)r * HID + c * 8));
            }
        }
        asm volatile("cp.async.commit_group;");
    };

    loadTile(0, 0);

    for (int kb = 0; kb < NKB; kb++) {
        const int b = kb & 1, onb = b ^ 1;
        asm volatile("cp.async.wait_group 0;");   // my loads for tile kb landed
        BAR_ARRIVE(1 + b);                        // A_b: my data for kb ready
        if (kb >= 1) BAR_SYNCN(3 + onb);          // F_onb: buffer onb freed
        if (kb + 1 < NKB) loadTile(kb + 1, onb);
        BAR_SYNCN(1 + b);                         // A_b: ALL data for kb visible

        const uint32_t stBase = smBase + b * (STGH * 2);

#pragma unroll
        for (int ks = 0; ks < 4; ks++) {
            const uint32_t kkb = ks * 32;
            uint32_t af[2][4], bf[8][2];
#pragma unroll
            for (int mt = 0; mt < 2; mt++)
                LDSM_X4(af[mt][0], af[mt][1], af[mt][2], af[mt][3],
                        stBase + offA[mt] + kkb);
#pragma unroll
            for (int p = 0; p < 4; p++)
                LDSM_X4(bf[2 * p][0], bf[2 * p][1], bf[2 * p + 1][0], bf[2 * p + 1][1],
                        stBase + offB[p] + kkb);
#pragma unroll
            for (int mt = 0; mt < 2; mt++)
#pragma unroll
                for (int nt = 0; nt < 8; nt++) {
                    asm volatile(
                        "mma.sync.aligned.m16n8k16.row.col.f32.f16.f16.f32 "
                        "{%0,%1,%2,%3}, {%4,%5,%6,%7}, {%8,%9}, {%0,%1,%2,%3};"
                        : "+f"(acc[mt][nt][0]), "+f"(acc[mt][nt][1]),
                          "+f"(acc[mt][nt][2]), "+f"(acc[mt][nt][3])
                        : "r"(af[mt][0]), "r"(af[mt][1]), "r"(af[mt][2]), "r"(af[mt][3]),
                          "r"(bf[nt][0]), "r"(bf[nt][1]));
                }
        }
        BAR_ARRIVE(3 + b);                        // F_b: I'm done reading buffer b
    }

    const float sc = SCALED ? 6.103515625e-5f : 1.0f;   // 2^-14

    // epilogue
#pragma unroll
    for (int mt = 0; mt < 2; mt++) {
        const int r0 = m0 + wm * 32 + mt * 16 + grp;
#pragma unroll
        for (int nt = 0; nt < 8; nt++) {
            const int c = n0 + wn * 64 + nt * 8 + qid * 2;
            const float bv0 = bias[c], bv1 = bias[c + 1];
            float v0 = acc[mt][nt][0] * sc + bv0, v1 = acc[mt][nt][1] * sc + bv1;
            float v2 = acc[mt][nt][2] * sc + bv0, v3 = acc[mt][nt][3] * sc + bv1;
            if (OUTH) {
                *(__half2*)(H + (size_t)r0 * HID + c)       = __floats2half2_rn(v0, v1);
                *(__half2*)(H + (size_t)(r0 + 8) * HID + c) = __floats2half2_rn(v2, v3);
            } else {
                __half2 ra = *(const __half2*)(residH + (size_t)r0 * HID + c);
                __half2 rb = *(const __half2*)(residH + (size_t)(r0 + 8) * HID + c);
                float2 raf = __half22float2(ra), rbf = __half22float2(rb);
                float2 oa = {v0 + raf.x, v1 + raf.y};
                float2 ob = {v2 + rbf.x, v3 + rbf.y};
                *(float2*)(Cf + (size_t)r0 * HID + c) = oa;
                *(float2*)(Cf + (size_t)(r0 + 8) * HID + c) = ob;
            }
        }
    }
}

// ============================================================================
// score_mma: out[m,h] = sum_k src[m,k]*(W[h,k]*(gate?g[b,k]:1)) + bias[h]
// Tensor-core skinny GEMM (N=16). Gated W resident in smem as fp16
// (row stride 1032 halves -> conflict-free LDSM); A 3-stage cp.async.
// 256 thr (8 warps x m16 = 128 rows/CTA), m16n8k16.
// ============================================================================
constexpr int SC_WROW = 1032;                 // Wg smem row stride (halves)
constexpr int SC_SROW = 72;                   // A smem row stride (halves)
constexpr int SC_NKT  = HID / 64;             // 16 K-tiles of 64
constexpr size_t SC_SMEM = (size_t)(16 * SC_WROW + 3 * 128 * SC_SROW) * 2; // 88320 B

__global__ void __launch_bounds__(256, 2) score_mma(
    const __half* __restrict__ src, const float* __restrict__ W,
    const float* __restrict__ bias, const float* __restrict__ gate,
    float* __restrict__ out)
{
    extern __shared__ __half ssc[];
    __half* sWg = ssc;                        // 16 x 1032
    __half* sA  = ssc + 16 * SC_WROW;         // 3 x 128 x 72
    const int tid = threadIdx.x, warp = tid >> 5, lane = tid & 31;
    const int row0 = blockIdx.x * 128;
    const int b = row0 / SEQ;

    // build gated fp16 weight in smem
    for (int i = tid; i < NHEAD * HID; i += 256) {
        const int h = i >> 10, k = i & 1023;
        float w = W[i];
        if (gate) w *= gate[b * HID + k];
        sWg[h * SC_WROW + k] = __float2half_rn(w);
    }

    const __half* Ab = src + (size_t)row0 * HID;
    auto loadA = [&](int kt, int s) {
        __half* sa = sA + s * 128 * SC_SROW;
        const __half* Ag = Ab + kt * 64;
#pragma unroll
        for (int i = 0; i < 4; i++) {          // 1024 granules of 16B
            const int id = tid + 256 * i;
            const int r = id >> 3, c = id & 7;
            uint32_t d = (uint32_t)__cvta_generic_to_shared(sa + r * SC_SROW + c * 8);
            asm volatile("cp.async.cg.shared.global [%0], [%1], 16;"
                         :: "r"(d), "l"(Ag + (size_t)r * HID + c * 8));
        }
        asm volatile("cp.async.commit_group;");
    };

    loadA(0, 0);
    loadA(1, 1);
    __syncthreads();                           // Wg visible to all warps

    const int lr = lane & 7;
    const int lh = (lane >> 3) & 1;
    const int lk = lane >> 4;
    const uint32_t offA = (uint32_t)(((warp * 16 + lh * 8 + lr) * SC_SROW + lk * 8) * 2);
    const uint32_t offBW = (uint32_t)(((lk * 8 + lr) * SC_WROW + lh * 8) * 2);
    const uint32_t smA = (uint32_t)__cvta_generic_to_shared(sA);
    const uint32_t smW = (uint32_t)__cvta_generic_to_shared(sWg);

    float acc0[4] = {0.f, 0.f, 0.f, 0.f};
    float acc1[4] = {0.f, 0.f, 0.f, 0.f};

    int s = 0;
    for (int kt = 0; kt < SC_NKT; kt++) {
        if (kt + 1 < SC_NKT) asm volatile("cp.async.wait_group 1;");
        else                 asm volatile("cp.async.wait_group 0;");
        __syncthreads();
        if (kt + 2 < SC_NKT) loadA(kt + 2, (s + 2) % 3);

        const uint32_t stA = smA + s * (128 * SC_SROW * 2);
#pragma unroll
        for (int ks = 0; ks < 4; ks++) {
            uint32_t a0, a1, a2, a3, b0, b1, b2, b3;
            LDSM_X4(a0, a1, a2, a3, stA + offA + ks * 32);
            LDSM_X4(b0, b1, b2, b3, smW + offBW + (uint32_t)((kt * 64 + ks * 16) * 2));
            asm volatile(
                "mma.sync.aligned.m16n8k16.row.col.f32.f16.f16.f32 "
                "{%0,%1,%2,%3}, {%4,%5,%6,%7}, {%8,%9}, {%0,%1,%2,%3};"
                : "+f"(acc0[0]), "+f"(acc0[1]), "+f"(acc0[2]), "+f"(acc0[3])
                : "r"(a0), "r"(a1), "r"(a2), "r"(a3), "r"(b0), "r"(b1));
            asm volatile(
                "mma.sync.aligned.m16n8k16.row.col.f32.f16.f16.f32 "
                "{%0,%1,%2,%3}, {%4,%5,%6,%7}, {%8,%9}, {%0,%1,%2,%3};"
                : "+f"(acc1[0]), "+f"(acc1[1]), "+f"(acc1[2]), "+f"(acc1[3])
                : "r"(a0), "r"(a1), "r"(a2), "r"(a3), "r"(b2), "r"(b3));
        }
        s = (s + 1) % 3;
    }

    const int grp = lane >> 2, qid = lane & 3;
    const int rlo = row0 + warp * 16 + grp;
    float2 bv0 = ((const float2*)bias)[qid];
    float2 bv1 = ((const float2*)bias)[4 + qid];
    float2 o;
    o.x = acc0[0] + bv0.x; o.y = acc0[1] + bv0.y;
    *(float2*)(out + (size_t)rlo * NHEAD + qid * 2) = o;
    o.x = acc0[2] + bv0.x; o.y = acc0[3] + bv0.y;
    *(float2*)(out + (size_t)(rlo + 8) * NHEAD + qid * 2) = o;
    o.x = acc1[0] + bv1.x; o.y = acc1[1] + bv1.y;
    *(float2*)(out + (size_t)rlo * NHEAD + 8 + qid * 2) = o;
    o.x = acc1[2] + bv1.x; o.y = acc1[3] + bv1.y;
    *(float2*)(out + (size_t)(rlo + 8) * NHEAD + 8 + qid * 2) = o;
}

// ============================================================================
// Combined fp32 -> fp16 conversion of X, Wq, Wk in ONE launch.
// 2 float4 granules per thread (MLP_p1=2, halved grid).
// ============================================================================
constexpr int N4_X   = MROWS * HID / 4;       // 8388608
constexpr int N4_W   = HID * HID / 4;         // 262144
constexpr int N4_TOT = N4_X + 2 * N4_W;       // 8912896

__global__ void f2h3_kernel(const float* __restrict__ X,
                            const float* __restrict__ Wq,
                            const float* __restrict__ Wk,
                            __half* __restrict__ xh,
                            __half* __restrict__ wqh,
                            __half* __restrict__ wkh)
{
    const int base = blockIdx.x * 512 + threadIdx.x;
#pragma unroll
    for (int u = 0; u < 2; u++) {
        const int i = base + u * 256;
        if (i >= N4_TOT) return;
        const float* src; __half* dst; int j;
        if (i < N4_X)             { src = X;  dst = xh;  j = i; }
        else if (i < N4_X + N4_W) { src = Wq; dst = wqh; j = i - N4_X; }
        else                      { src = Wk; dst = wkh; j = i - N4_X - N4_W; }
        float4 v = ((const float4*)src)[j];
        ((__half2*)dst)[2 * j]     = __floats2half2_rn(v.x, v.y);
        ((__half2*)dst)[2 * j + 1] = __floats2half2_rn(v.z, v.w);
    }
}

// ============================================================================
// accum: per (bh, 256-row chunk) chunk-local softmax + partial pool.
// exp computed ONCE per row (stored in smem), pooling is pure LDG+FMA.
// [verified-best: ACH=16, 256 threads, accum 21.3us / total 661.6us]
// ============================================================================
constexpr int ACH = 16;                       // chunks per (b,h)
constexpr int ACS = SEQ / ACH;                // 256 rows per chunk

__global__ void accum_kernel(const __half* __restrict__ src,
                             const float* __restrict__ scores,
                             const float* __restrict__ mask,
                             float* __restrict__ part, float2* __restrict__ ms)
{
    __shared__ float  sL[ACS];
    __shared__ float  red[256];
    __shared__ float2 red2[256];
    const int blk = blockIdx.x, bh = blk >> 4, ch = blk & 15;
    const int b = bh >> 4, h = bh & 15;
    const int t = threadIdx.x;
    const int s0 = ch * ACS;
    const float* sc = scores + ((size_t)(b * SEQ + s0)) * NHEAD + h;
    const float* mk = mask + b * SEQ + s0;

    // logits + chunk max
    const float l = sc[(size_t)t * NHEAD] * 0.125f + mk[t];
    red[t] = l; __syncthreads();
    for (int o = 128; o; o >>= 1) { if (t < o) red[t] = fmaxf(red[t], red[t + o]); __syncthreads(); }
    const float mc = red[0]; __syncthreads();

    // exp once per row -> smem weights; chunk sum
    const float e = __expf(l - mc);
    sL[t] = e;
    red[t] = e; __syncthreads();
    for (int o = 128; o; o >>= 1) { if (t < o) red[t] += red[t + o]; __syncthreads(); }
    const float ssum = red[0];

    // weighted pool (unnormalized): 32 d2-threads x 8 row-groups, half2 loads
    const int d2 = t & 31, sg = t >> 5;
    const __half2* base = (const __half2*)(src + (size_t)(b * SEQ + s0) * HID + h * 64) + d2;
    float2 acc = {0.f, 0.f};
    for (int s = sg; s < ACS; s += 8) {
        const float w = sL[s];
        float2 v = __half22float2(base[(size_t)s * (HID / 2)]);
        acc.x += w * v.x; acc.y += w * v.y;
    }
    red2[t] = acc; __syncthreads();
    if (sg < 4) { red2[t].x += red2[t + 128].x; red2[t].y += red2[t + 128].y; } __syncthreads();
    if (sg < 2) { red2[t].x += red2[t + 64].x;  red2[t].y += red2[t + 64].y; }  __syncthreads();
    if (sg == 0) {
        float2 r = red2[t];
        r.x += red2[t + 32].x; r.y += red2[t + 32].y;
        ((float2*)(part + (size_t)blk * 64))[d2] = r;
        if (d2 == 0) ms[blk] = make_float2(mc, ssum);
    }
}

__global__ void finalize_kernel(const float* __restrict__ part,
                                const float2* __restrict__ ms,
                                const float* __restrict__ postgate, float* __restrict__ out)
{
    const int idx = blockIdx.x * 256 + threadIdx.x;   // 8192
    const int bh = idx >> 6, d = idx & 63;
    float2 mv[ACH];
    float M = -1e30f;
#pragma unroll
    for (int c = 0; c < ACH; c++) { mv[c] = ms[bh * ACH + c]; M = fmaxf(M, mv[c].x); }
    float num = 0.f, den = 0.f;
#pragma unroll
    for (int c = 0; c < ACH; c++) {
        const float w = __expf(mv[c].x - M);
        num += w * part[(size_t)(bh * ACH + c) * 64 + d];
        den += w * mv[c].y;
    }
    float v = num / den;
    if (postgate) v *= postgate[idx];
    out[idx] = v;
}

// wtgh[b,n,k] = (half)(Wt[n,k] * pk[b,k] * 2^14)   (scale avoids fp16 subnormals)
__global__ void wtg_kernel(const float* __restrict__ Wt, const float* __restrict__ pk,
                           __half* __restrict__ wtgh)
{
    const size_t i4 = (size_t)blockIdx.x * 256 + threadIdx.x;  // 2,097,152
    const int j4 = (int)(i4 & 255);
    const int n  = (int)((i4 >> 8) & 1023);
    const int b  = (int)(i4 >> 18);
    float4 w = ((const float4*)Wt)[n * 256 + j4];
    float4 g = ((const float4*)pk)[b * 256 + j4];
    const float S = 16384.0f;
    __half2 h0 = __floats2half2_rn(w.x * g.x * S, w.y * g.y * S);
    __half2 h1 = __floats2half2_rn(w.z * g.z * S, w.w * g.w * S);
    ((__half2*)wtgh)[2 * i4]     = h0;
    ((__half2*)wtgh)[2 * i4 + 1] = h1;
}

// ============================================================================
extern "C" void kernel_launch(void* const* d_in, const int* in_sizes, int n_in,
                              void* d_out, int out_size)
{
    const float* X    = (const float*)d_in[0];
    const float* mask = (const float*)d_in[1];
    const float* Wq   = (const float*)d_in[2];
    const float* bq   = (const float*)d_in[3];
    const float* Wqa  = (const float*)d_in[4];
    const float* bqa  = (const float*)d_in[5];
    const float* Wk   = (const float*)d_in[6];
    const float* bk   = (const float*)d_in[7];
    const float* Wka  = (const float*)d_in[8];
    const float* bka  = (const float*)d_in[9];
    const float* Wt   = (const float*)d_in[10];
    const float* bt   = (const float*)d_in[11];
    float* out = (float*)d_out;

    float *qs, *ks, *pq, *pk, *part;
    float2 *ms;
    __half *xh, *mqh, *mkh, *wqh, *wkh, *wtgh;
    cudaGetSymbolAddress((void**)&qs, g_qs);
    cudaGetSymbolAddress((void**)&ks, g_ks);
    cudaGetSymbolAddress((void**)&pq, g_pq);
    cudaGetSymbolAddress((void**)&pk, g_pk);
    cudaGetSymbolAddress((void**)&part, g_part);
    cudaGetSymbolAddress((void**)&ms, g_ms);
    cudaGetSymbolAddress((void**)&xh, g_xh);
    cudaGetSymbolAddress((void**)&mqh, g_mqh);
    cudaGetSymbolAddress((void**)&mkh, g_mkh);
    cudaGetSymbolAddress((void**)&wqh, g_wqh);
    cudaGetSymbolAddress((void**)&wkh, g_wkh);
    cudaGetSymbolAddress((void**)&wtgh, g_wtgh);

    cudaFuncSetAttribute(gemm_fp16<true, false, true, false>,
                         cudaFuncAttributeMaxDynamicSharedMemorySize, (int)GEMM_SMEM);
    cudaFuncSetAttribute(gemm_fp16<false, true, false, true>,
                         cudaFuncAttributeMaxDynamicSharedMemorySize, (int)GEMM_SMEM);
    cudaFuncSetAttribute(score_mma,
                         cudaFuncAttributeMaxDynamicSharedMemorySize, (int)SC_SMEM);

    const float* nullf = nullptr;

    // 0) single fused fp32->fp16 conversion (X, Wq, Wk)
    f2h3_kernel<<<(N4_TOT + 511) / 512, 256>>>(X, Wq, Wk, xh, wqh, wkh);

    // 1) fused: mqh = X@Wq^T + bq ; mkh = X@Wk^T + bk  (fp16 outputs)
    gemm_fp16<true, false, true, false><<<dim3(16, MROWS / BM), 128, GEMM_SMEM>>>(
        xh, wqh, wkh, bq, bk, (const __half*)nullptr, (float*)nullptr, mqh, mkh);

    // 2) q scores -> pooled_q (chunk-local softmax)
    score_mma<<<MROWS / 128, 256, SC_SMEM>>>(mqh, Wqa, bqa, nullf, qs);
    accum_kernel<<<BATCH * NHEAD * ACH, 256>>>(mqh, qs, mask, part, ms);
    finalize_kernel<<<BATCH * HID / 256, 256>>>(part, ms, nullf, pq);

    // 3) qk scores (gate folded into Wka) -> pooled_k (post-gate pq)
    score_mma<<<MROWS / 128, 256, SC_SMEM>>>(mkh, Wka, bka, pq, ks);
    accum_kernel<<<BATCH * NHEAD * ACH, 256>>>(mkh, ks, mask, part, ms);
    finalize_kernel<<<BATCH * HID / 256, 256>>>(part, ms, pq, pk);

    // 4) wtgh = Wt * pk_full[b] * 2^14 ; out = mqh @ wtgh[b]^T * 2^-14 + bt + mqh
    wtg_kernel<<<(BATCH * HID * HID / 4) / 256, 256>>>(Wt, pk, wtgh);
    gemm_fp16<false, true, false, true><<<dim3(8, MROWS / BM), 128, GEMM_SMEM>>>(
        mqh, wtgh, (const __half*)nullptr, bt, nullf, mqh, out,
        (__half*)nullptr, (__half*)nullptr);
}